// round 16
// baseline (speedup 1.0000x reference)
#include <cuda_runtime.h>
#include <cuda_fp16.h>
#include <cstdint>
#include <math.h>

#define NTOK 8192
#define CDIM 1024
#define HDIM 4096
#define NEXP 8

#define BM 128
#define BN 128
#define BK 64
#define STAGES 3
#define T1 (CDIM / BK)   // 16
#define T2 (HDIM / BK)   // 64
#define MSEGS 4          // gemm1 m-tiles per block

// padded fp16 smem rows: A row 72 halves (144B), B row 136 halves (272B)
#define A_ROW_B 144
#define B_ROW_B 272
#define A_BYTES (BM * A_ROW_B)          // 18432
#define B_BYTES (BK * B_ROW_B)          // 17408
#define STAGE_BYTES (A_BYTES + B_BYTES) // 35840
#define SMEM_DYN (STAGES * STAGE_BYTES) // 107520  (x2 CTAs = 215KB/SM)

// ---------------- scratch ----------------
__device__ int    g_counts[NEXP];        // statically zero-initialized; re-zeroed by combine
__device__ int    g_list[NEXP * NTOK];
__device__ float  g_wts[NTOK * 2];
__device__ __half g_xh[(size_t)NTOK * CDIM];
__device__ __half g_w1h[(size_t)NEXP * CDIM * HDIM];
__device__ __half g_w2h[(size_t)NEXP * HDIM * CDIM];
__device__ __half g_hh[(size_t)2 * NTOK * HDIM];
__device__ __half g_yh[(size_t)2 * NTOK * CDIM];

// ---------------- helpers ----------------
__device__ __forceinline__ uint32_t smem_u32(const void* p) {
  uint32_t a;
  asm("{ .reg .u64 t; cvta.to.shared.u64 t, %1; cvt.u32.u64 %0, t; }" : "=r"(a) : "l"(p));
  return a;
}
__device__ __forceinline__ void cp16(uint32_t dst, const void* src) {
  asm volatile("cp.async.cg.shared.global [%0], [%1], 16;" :: "r"(dst), "l"(src));
}
#define CP_COMMIT() asm volatile("cp.async.commit_group;")
#define CP_WAIT1()  asm volatile("cp.async.wait_group 1;")

__device__ __forceinline__ void ldsm4(uint32_t r[4], uint32_t addr) {
  asm volatile("ldmatrix.sync.aligned.m8n8.x4.shared.b16 {%0,%1,%2,%3}, [%4];"
               : "=r"(r[0]), "=r"(r[1]), "=r"(r[2]), "=r"(r[3]) : "r"(addr));
}
__device__ __forceinline__ void ldsm4t(uint32_t r[4], uint32_t addr) {
  asm volatile("ldmatrix.sync.aligned.m8n8.x4.trans.shared.b16 {%0,%1,%2,%3}, [%4];"
               : "=r"(r[0]), "=r"(r[1]), "=r"(r[2]), "=r"(r[3]) : "r"(addr));
}
__device__ __forceinline__ void mma16816(float c[4], const uint32_t a[4], uint32_t b0, uint32_t b1) {
  asm volatile(
      "mma.sync.aligned.m16n8k16.row.col.f32.f16.f16.f32 "
      "{%0,%1,%2,%3}, {%4,%5,%6,%7}, {%8,%9}, {%0,%1,%2,%3};"
      : "+f"(c[0]), "+f"(c[1]), "+f"(c[2]), "+f"(c[3])
      : "r"(a[0]), "r"(a[1]), "r"(a[2]), "r"(a[3]), "r"(b0), "r"(b1));
}

// ---------------- fused prep: W1/W2 -> fp16 conversion || gating (+x->fp16) ---
#define WBLOCKS ((NEXP * CDIM * HDIM) / 8 / 256)
#define GBLOCKS (NTOK / 8)
__global__ void prep_kernel(const float* __restrict__ W1, const float* __restrict__ W2,
                            __half* __restrict__ d1, __half* __restrict__ d2,
                            const float* __restrict__ x, const float* __restrict__ Wg,
                            __half* __restrict__ xh) {
  if (blockIdx.x < 2 * WBLOCKS) {
    const bool second = blockIdx.x >= WBLOCKS;
    const float* s = second ? W2 : W1;
    __half* d = second ? d2 : d1;
    size_t i = (size_t)(second ? blockIdx.x - WBLOCKS : blockIdx.x) * blockDim.x + threadIdx.x;
    float4 v0 = __ldcs((const float4*)s + i * 2);
    float4 v1 = __ldcs((const float4*)s + i * 2 + 1);
    __half2 h[4];
    h[0] = __floats2half2_rn(v0.x, v0.y);
    h[1] = __floats2half2_rn(v0.z, v0.w);
    h[2] = __floats2half2_rn(v1.x, v1.y);
    h[3] = __floats2half2_rn(v1.z, v1.w);
    ((uint4*)d)[i] = *(uint4*)h;
    return;
  }

  // ---- gating path ----
  const int blk = blockIdx.x - 2 * WBLOCKS;
  const int warp = threadIdx.x >> 5;
  const int lane = threadIdx.x & 31;
  const int n = blk * 8 + warp;
  const float* xr = x + (size_t)n * CDIM;
  __half* xhr = xh + (size_t)n * CDIM;

  float acc[NEXP];
#pragma unroll
  for (int e = 0; e < NEXP; e++) acc[e] = 0.f;
  for (int c = lane; c < CDIM; c += 32) {
    float xv = xr[c];
    xhr[c] = __float2half_rn(xv);
    float4 w0 = *(const float4*)(Wg + c * NEXP);
    float4 w1 = *(const float4*)(Wg + c * NEXP + 4);
    acc[0] += xv * w0.x; acc[1] += xv * w0.y; acc[2] += xv * w0.z; acc[3] += xv * w0.w;
    acc[4] += xv * w1.x; acc[5] += xv * w1.y; acc[6] += xv * w1.z; acc[7] += xv * w1.w;
  }
#pragma unroll
  for (int e = 0; e < NEXP; e++)
#pragma unroll
    for (int o = 16; o > 0; o >>= 1)
      acc[e] += __shfl_xor_sync(0xffffffffu, acc[e], o);

  if (lane == 0) {
    float mx = acc[0];
#pragma unroll
    for (int e = 1; e < NEXP; e++) mx = fmaxf(mx, acc[e]);
    float p[NEXP], Z = 0.f;
#pragma unroll
    for (int e = 0; e < NEXP; e++) { p[e] = expf(acc[e] - mx); Z += p[e]; }
    float inv = 1.f / Z;
#pragma unroll
    for (int e = 0; e < NEXP; e++) p[e] *= inv;
    int i0 = 0; float b0 = p[0];
#pragma unroll
    for (int e = 1; e < NEXP; e++) if (p[e] > b0) { b0 = p[e]; i0 = e; }
    int i1 = -1; float b1 = -1.f;
#pragma unroll
    for (int e = 0; e < NEXP; e++) if (e != i0 && p[e] > b1) { b1 = p[e]; i1 = e; }
    float s = b0 + b1 + 1e-9f;
    int pos0 = atomicAdd(&g_counts[i0], 1);
    g_list[i0 * NTOK + pos0] = n * 2;
    g_wts[n * 2] = b0 / s;
    int pos1 = atomicAdd(&g_counts[i1], 1);
    g_list[i1 * NTOK + pos1] = n * 2 + 1;
    g_wts[n * 2 + 1] = b1 / s;
  }
}

// ======== shared GEMM compute (R10-proven warp tile 64x32) ========
#define COMPUTE_TILE(sbuf)                                                        \
  {                                                                               \
    uint32_t as_ = smem_base + (sbuf)*STAGE_BYTES;                                \
    uint32_t bs_ = as_ + A_BYTES;                                                 \
    uint32_t arow_ = (lane & 15), asel_ = (lane >> 4) * 16;                       \
    _Pragma("unroll")                                                             \
    for (int kk = 0; kk < BK; kk += 16) {                                         \
      uint32_t af_[4][4], bf_[2][4];                                              \
      _Pragma("unroll")                                                           \
      for (int mi = 0; mi < 4; mi++)                                              \
        ldsm4(af_[mi], as_ + (wm + mi * 16 + arow_) * A_ROW_B + kk * 2 + asel_);  \
      _Pragma("unroll")                                                           \
      for (int nc = 0; nc < 2; nc++)                                              \
        ldsm4t(bf_[nc], bs_ + (kk + arow_) * B_ROW_B + (wn + nc * 16) * 2 + asel_);\
      _Pragma("unroll")                                                           \
      for (int mi = 0; mi < 4; mi++)                                              \
        _Pragma("unroll")                                                         \
        for (int nc = 0; nc < 2; nc++) {                                          \
          mma16816(acc[mi][2 * nc],     af_[mi], bf_[nc][0], bf_[nc][1]);         \
          mma16816(acc[mi][2 * nc + 1], af_[mi], bf_[nc][2], bf_[nc][3]);         \
        }                                                                         \
    }                                                                             \
  }

// generic load tile (used by gemm2)
#define LOAD_TILE(AROWS, ASTRIDE, BPTR, BSTRIDE, kt, sbuf)                        \
  {                                                                               \
    uint32_t as_ = smem_base + (sbuf)*STAGE_BYTES;                                \
    uint32_t bs_ = as_ + A_BYTES;                                                 \
    _Pragma("unroll")                                                             \
    for (int i_ = 0; i_ < 4; i_++) {                                              \
      int j_ = tid + 256 * i_;                                                    \
      int r_ = j_ >> 3, cc_ = j_ & 7;                                             \
      cp16(as_ + r_ * A_ROW_B + cc_ * 16, (AROWS) + (size_t)(ASTRIDE)[r_] * (size_t)(kt##_stride) + (kt) + cc_ * 8); \
    }                                                                             \
    _Pragma("unroll")                                                             \
    for (int i_ = 0; i_ < 4; i_++) {                                              \
      int j_ = tid + 256 * i_;                                                    \
      int r_ = j_ >> 4, cc_ = j_ & 15;                                            \
      cp16(bs_ + r_ * B_ROW_B + cc_ * 16, (BPTR) + (size_t)((kt) + r_) * (BSTRIDE) + cc_ * 8); \
    }                                                                             \
  }

#define GEMM_MAINLOOP(AROWS, ASTRIDE, BPTR, BSTRIDE, TT)   \
  _Pragma("unroll")                                        \
  for (int s = 0; s < STAGES - 1; s++) {                   \
    int kt = s * BK;                                       \
    LOAD_TILE(AROWS, ASTRIDE, BPTR, BSTRIDE, kt, s);       \
    CP_COMMIT();                                           \
  }                                                        \
  for (int t = 0; t < (TT); t++) {                         \
    CP_WAIT1();                                            \
    __syncthreads();                                       \
    int tn = t + STAGES - 1;                               \
    if (tn < (TT)) {                                       \
      int kt = tn * BK;                                    \
      LOAD_TILE(AROWS, ASTRIDE, BPTR, BSTRIDE, kt, tn % STAGES); \
    }                                                      \
    CP_COMMIT();                                           \
    COMPUTE_TILE(t % STAGES);                              \
  }

// gemm1 tile loader: segment = tn>>4 selects the A-row block, kt = (tn&15)*BK
#define LOAD_TILE1(tn, sbuf)                                                      \
  {                                                                               \
    uint32_t as_ = smem_base + (sbuf)*STAGE_BYTES;                                \
    uint32_t bs_ = as_ + A_BYTES;                                                 \
    const int seg_ = (tn) >> 4;                                                   \
    const int kt_ = ((tn) & 15) * BK;                                             \
    _Pragma("unroll")                                                             \
    for (int i_ = 0; i_ < 4; i_++) {                                              \
      int j_ = tid + 256 * i_;                                                    \
      int r_ = j_ >> 3, cc_ = j_ & 7;                                             \
      cp16(as_ + r_ * A_ROW_B + cc_ * 16,                                         \
           xh + (size_t)s_tok[seg_ * BM + r_] * CDIM + kt_ + cc_ * 8);            \
    }                                                                             \
    _Pragma("unroll")                                                             \
    for (int i_ = 0; i_ < 4; i_++) {                                              \
      int j_ = tid + 256 * i_;                                                    \
      int r_ = j_ >> 4, cc_ = j_ & 15;                                            \
      cp16(bs_ + r_ * B_ROW_B + cc_ * 16,                                         \
           BW + (size_t)(kt_ + r_) * HDIM + cc_ * 8);                             \
    }                                                                             \
  }

// ---------------- GEMM1  h = relu(gather(xh) @ W1h) — MSEGS m-tiles per block --
__global__ __launch_bounds__(256, 2) void gemm1_kernel(const __half* __restrict__ xh,
                                                       const __half* __restrict__ W1h) {
  const int e = blockIdx.z;
  const int cnt = g_counts[e];
  const int m0 = blockIdx.y * (MSEGS * BM);
  if (m0 >= cnt) return;
  int nseg = 1;
#pragma unroll
  for (int s = 1; s < MSEGS; s++) nseg += (m0 + s * BM < cnt) ? 1 : 0;
  const int TT = nseg * T1;
  const int n0 = blockIdx.x * BN;
  int base = 0;
#pragma unroll
  for (int i = 0; i < NEXP; i++) base += (i < e) ? g_counts[i] : 0;

  extern __shared__ char smem[];
  __shared__ int s_tok[MSEGS * BM];
  const uint32_t smem_base = smem_u32(smem);
  const int tid = threadIdx.x, wid = tid >> 5, lane = tid & 31;
  const int wm = (wid >> 2) * 64, wn = (wid & 3) * 32;

#pragma unroll
  for (int s = 0; s < MSEGS / 2; s++) {
    int j = s * 256 + tid;
    int m = m0 + j;
    int idx = (m < cnt) ? m : (cnt - 1);
    s_tok[j] = g_list[e * NTOK + idx] >> 1;
  }
  __syncthreads();

  const __half* BW = W1h + (size_t)e * CDIM * HDIM + n0;

  float acc[4][4][4];
#pragma unroll
  for (int a = 0; a < 4; a++)
#pragma unroll
    for (int b = 0; b < 4; b++)
#pragma unroll
      for (int c = 0; c < 4; c++) acc[a][b][c] = 0.f;

  const int rquad = lane >> 2, cpair = (lane & 3) * 2;

#pragma unroll
  for (int s = 0; s < STAGES - 1; s++) {
    LOAD_TILE1(s, s);
    CP_COMMIT();
  }
  for (int t = 0; t < TT; t++) {
    CP_WAIT1();
    __syncthreads();
    int tn = t + STAGES - 1;
    if (tn < TT) { LOAD_TILE1(tn, tn % STAGES); }
    CP_COMMIT();
    COMPUTE_TILE(t % STAGES);

    if ((t & (T1 - 1)) == (T1 - 1)) {
      // epilogue for segment t>>4: relu -> fp16 h rows, then reset acc
      const int mseg = m0 + (t >> 4) * BM;
#pragma unroll
      for (int mi = 0; mi < 4; mi++) {
        int rl0 = wm + mi * 16 + rquad;
#pragma unroll
        for (int ni = 0; ni < 4; ni++) {
          int col = n0 + wn + ni * 8 + cpair;
          if (mseg + rl0 < cnt) {
            __half2 h = __floats2half2_rn(fmaxf(acc[mi][ni][0], 0.f), fmaxf(acc[mi][ni][1], 0.f));
            *(__half2*)(g_hh + (size_t)(base + mseg + rl0) * HDIM + col) = h;
          }
          if (mseg + rl0 + 8 < cnt) {
            __half2 h = __floats2half2_rn(fmaxf(acc[mi][ni][2], 0.f), fmaxf(acc[mi][ni][3], 0.f));
            *(__half2*)(g_hh + (size_t)(base + mseg + rl0 + 8) * HDIM + col) = h;
          }
        }
      }
#pragma unroll
      for (int a = 0; a < 4; a++)
#pragma unroll
        for (int b = 0; b < 4; b++)
#pragma unroll
          for (int c = 0; c < 4; c++) acc[a][b][c] = 0.f;
    }
  }
}

// ---------------- GEMM2  y = w * (h @ W2h), stored fp16 ----------------
__global__ __launch_bounds__(256, 2) void gemm2_kernel(const __half* __restrict__ W2h) {
  const int e = blockIdx.z;
  const int cnt = g_counts[e];
  const int m0 = blockIdx.y * BM;
  if (m0 >= cnt) return;
  const int n0 = blockIdx.x * BN;
  int base = 0;
#pragma unroll
  for (int i = 0; i < NEXP; i++) base += (i < e) ? g_counts[i] : 0;

  extern __shared__ char smem[];
  __shared__ int s_row[BM];
  const uint32_t smem_base = smem_u32(smem);
  const int tid = threadIdx.x, wid = tid >> 5, lane = tid & 31;
  const int wm = (wid >> 2) * 64, wn = (wid & 3) * 32;

  if (tid < BM) {
    int m = m0 + tid;
    int idx = (m < cnt) ? m : (cnt - 1);
    s_row[tid] = base + idx;
  }
  __syncthreads();

  const __half* BW = W2h + (size_t)e * HDIM * CDIM + n0;
  const __half* Ah = g_hh;
  const int kt_stride = HDIM;

  float acc[4][4][4];
#pragma unroll
  for (int a = 0; a < 4; a++)
#pragma unroll
    for (int b = 0; b < 4; b++)
#pragma unroll
      for (int c = 0; c < 4; c++) acc[a][b][c] = 0.f;

  GEMM_MAINLOOP(Ah, s_row, BW, CDIM, T2);

  // epilogue: gate-weight scale, scatter fp16 pairs to per-assignment y row
  const int rquad = lane >> 2, cpair = (lane & 3) * 2;
#pragma unroll
  for (int mi = 0; mi < 4; mi++) {
    int rl0 = wm + mi * 16 + rquad;
#pragma unroll
    for (int half = 0; half < 2; half++) {
      int rl = rl0 + half * 8;
      if (m0 + rl < cnt) {
        int v = g_list[e * NTOK + m0 + rl];
        float w = g_wts[v];
        __half* yrow = g_yh + (size_t)v * CDIM + n0 + wn;
#pragma unroll
        for (int ni = 0; ni < 4; ni++) {
          __half2 o = __floats2half2_rn(w * acc[mi][ni][2 * half],
                                        w * acc[mi][ni][2 * half + 1]);
          *(__half2*)(yrow + ni * 8 + cpair) = o;
        }
      }
    }
  }
}

// ---------------- combine: out[n] = fp32(y[2n]) + fp32(y[2n+1]) ---------------
// Also re-zeros the expert counters for the next call (they are only read
// before this point in the pipeline; static zero-init covers the first call).
__global__ void combine_kernel(float* __restrict__ out) {
  if (blockIdx.x == 0 && threadIdx.x < NEXP) g_counts[threadIdx.x] = 0;
  int i = blockIdx.x * blockDim.x + threadIdx.x;  // 8-float chunk index
  int c8 = i & (CDIM / 8 - 1);
  int n = i >> 7;
  uint4 a = __ldcs((const uint4*)(g_yh + (size_t)(2 * n) * CDIM) + c8);
  uint4 b = __ldcs((const uint4*)(g_yh + (size_t)(2 * n + 1) * CDIM) + c8);
  const __half2* ah = (const __half2*)&a;
  const __half2* bh = (const __half2*)&b;
  float4 o0, o1;
  {
    float2 p = __half22float2(ah[0]), q = __half22float2(bh[0]);
    o0.x = p.x + q.x; o0.y = p.y + q.y;
    p = __half22float2(ah[1]); q = __half22float2(bh[1]);
    o0.z = p.x + q.x; o0.w = p.y + q.y;
    p = __half22float2(ah[2]); q = __half22float2(bh[2]);
    o1.x = p.x + q.x; o1.y = p.y + q.y;
    p = __half22float2(ah[3]); q = __half22float2(bh[3]);
    o1.z = p.x + q.x; o1.w = p.y + q.y;
  }
  ((float4*)out)[i * 2] = o0;
  ((float4*)out)[i * 2 + 1] = o1;
}

// ---------------- launch ----------------
extern "C" void kernel_launch(void* const* d_in, const int* in_sizes, int n_in,
                              void* d_out, int out_size) {
  const float* x  = (const float*)d_in[0];
  const float* Wg = (const float*)d_in[1];
  const float* W1 = (const float*)d_in[2];
  const float* W2 = (const float*)d_in[3];
  float* out = (float*)d_out;

  cudaFuncSetAttribute(gemm1_kernel, cudaFuncAttributeMaxDynamicSharedMemorySize, SMEM_DYN);
  cudaFuncSetAttribute(gemm2_kernel, cudaFuncAttributeMaxDynamicSharedMemorySize, SMEM_DYN);

  __half* xh = nullptr; __half* w1h = nullptr; __half* w2h = nullptr;
  cudaGetSymbolAddress((void**)&xh, g_xh);
  cudaGetSymbolAddress((void**)&w1h, g_w1h);
  cudaGetSymbolAddress((void**)&w2h, g_w2h);

  // 4 launches: prep(cvt||gating) -> gemm1 -> gemm2 -> combine(+count reset)
  prep_kernel<<<2 * WBLOCKS + GBLOCKS, 256>>>(W1, W2, w1h, w2h, x, Wg, xh);
  gemm1_kernel<<<dim3(HDIM / BN, NTOK / (MSEGS * BM), NEXP), 256, SMEM_DYN>>>(xh, w1h);
  gemm2_kernel<<<dim3(CDIM / BN, NTOK / BM, NEXP), 256, SMEM_DYN>>>(w2h);
  combine_kernel<<<NTOK * CDIM / 8 / 256, 256>>>(out);
}

// round 17
// speedup vs baseline: 1.0186x; 1.0186x over previous
#include <cuda_runtime.h>
#include <cuda_fp16.h>
#include <cstdint>
#include <math.h>

#define NTOK 8192
#define CDIM 1024
#define HDIM 4096
#define NEXP 8

#define BM 128
#define BN 128
#define BK 64
#define STAGES 3
#define T1 (CDIM / BK)   // 16
#define T2 (HDIM / BK)   // 64
#define MSEGS 2          // gemm1 m-tiles per block (R15-proven sweet spot)

// padded fp16 smem rows: A row 72 halves (144B), B row 136 halves (272B)
#define A_ROW_B 144
#define B_ROW_B 272
#define A_BYTES (BM * A_ROW_B)          // 18432
#define B_BYTES (BK * B_ROW_B)          // 17408
#define STAGE_BYTES (A_BYTES + B_BYTES) // 35840
#define SMEM_DYN (STAGES * STAGE_BYTES) // 107520  (x2 CTAs = 215KB/SM)

// ---------------- scratch ----------------
__device__ int    g_counts[NEXP];        // statically zero-init; re-zeroed by combine
__device__ int    g_list[NEXP * NTOK];
__device__ float  g_wts[NTOK * 2];
__device__ __half g_xh[(size_t)NTOK * CDIM];
__device__ __half g_w1h[(size_t)NEXP * CDIM * HDIM];
__device__ __half g_w2h[(size_t)NEXP * HDIM * CDIM];
__device__ __half g_hh[(size_t)2 * NTOK * HDIM];
__device__ __half g_yh[(size_t)2 * NTOK * CDIM];

// ---------------- helpers ----------------
__device__ __forceinline__ uint32_t smem_u32(const void* p) {
  uint32_t a;
  asm("{ .reg .u64 t; cvta.to.shared.u64 t, %1; cvt.u32.u64 %0, t; }" : "=r"(a) : "l"(p));
  return a;
}
__device__ __forceinline__ void cp16(uint32_t dst, const void* src) {
  asm volatile("cp.async.cg.shared.global [%0], [%1], 16;" :: "r"(dst), "l"(src));
}
#define CP_COMMIT() asm volatile("cp.async.commit_group;")
#define CP_WAIT1()  asm volatile("cp.async.wait_group 1;")

__device__ __forceinline__ void ldsm4(uint32_t r[4], uint32_t addr) {
  asm volatile("ldmatrix.sync.aligned.m8n8.x4.shared.b16 {%0,%1,%2,%3}, [%4];"
               : "=r"(r[0]), "=r"(r[1]), "=r"(r[2]), "=r"(r[3]) : "r"(addr));
}
__device__ __forceinline__ void ldsm4t(uint32_t r[4], uint32_t addr) {
  asm volatile("ldmatrix.sync.aligned.m8n8.x4.trans.shared.b16 {%0,%1,%2,%3}, [%4];"
               : "=r"(r[0]), "=r"(r[1]), "=r"(r[2]), "=r"(r[3]) : "r"(addr));
}
__device__ __forceinline__ void mma16816(float c[4], const uint32_t a[4], uint32_t b0, uint32_t b1) {
  asm volatile(
      "mma.sync.aligned.m16n8k16.row.col.f32.f16.f16.f32 "
      "{%0,%1,%2,%3}, {%4,%5,%6,%7}, {%8,%9}, {%0,%1,%2,%3};"
      : "+f"(c[0]), "+f"(c[1]), "+f"(c[2]), "+f"(c[3])
      : "r"(a[0]), "r"(a[1]), "r"(a[2]), "r"(a[3]), "r"(b0), "r"(b1));
}

// ---------------- fused prep: W1/W2 -> fp16 conversion || gating (+x->fp16) ---
#define WBLOCKS ((NEXP * CDIM * HDIM) / 8 / 256)
#define GBLOCKS (NTOK / 8)
__global__ void prep_kernel(const float* __restrict__ W1, const float* __restrict__ W2,
                            __half* __restrict__ d1, __half* __restrict__ d2,
                            const float* __restrict__ x, const float* __restrict__ Wg,
                            __half* __restrict__ xh) {
  if (blockIdx.x < 2 * WBLOCKS) {
    const bool second = blockIdx.x >= WBLOCKS;
    const float* s = second ? W2 : W1;
    __half* d = second ? d2 : d1;
    size_t i = (size_t)(second ? blockIdx.x - WBLOCKS : blockIdx.x) * blockDim.x + threadIdx.x;
    float4 v0 = __ldcs((const float4*)s + i * 2);
    float4 v1 = __ldcs((const float4*)s + i * 2 + 1);
    __half2 h[4];
    h[0] = __floats2half2_rn(v0.x, v0.y);
    h[1] = __floats2half2_rn(v0.z, v0.w);
    h[2] = __floats2half2_rn(v1.x, v1.y);
    h[3] = __floats2half2_rn(v1.z, v1.w);
    ((uint4*)d)[i] = *(uint4*)h;
    return;
  }

  // ---- gating path ----
  const int blk = blockIdx.x - 2 * WBLOCKS;
  const int warp = threadIdx.x >> 5;
  const int lane = threadIdx.x & 31;
  const int n = blk * 8 + warp;
  const float* xr = x + (size_t)n * CDIM;
  __half* xhr = xh + (size_t)n * CDIM;

  float acc[NEXP];
#pragma unroll
  for (int e = 0; e < NEXP; e++) acc[e] = 0.f;
  for (int c = lane; c < CDIM; c += 32) {
    float xv = xr[c];
    xhr[c] = __float2half_rn(xv);
    float4 w0 = *(const float4*)(Wg + c * NEXP);
    float4 w1 = *(const float4*)(Wg + c * NEXP + 4);
    acc[0] += xv * w0.x; acc[1] += xv * w0.y; acc[2] += xv * w0.z; acc[3] += xv * w0.w;
    acc[4] += xv * w1.x; acc[5] += xv * w1.y; acc[6] += xv * w1.z; acc[7] += xv * w1.w;
  }
#pragma unroll
  for (int e = 0; e < NEXP; e++)
#pragma unroll
    for (int o = 16; o > 0; o >>= 1)
      acc[e] += __shfl_xor_sync(0xffffffffu, acc[e], o);

  if (lane == 0) {
    float mx = acc[0];
#pragma unroll
    for (int e = 1; e < NEXP; e++) mx = fmaxf(mx, acc[e]);
    float p[NEXP], Z = 0.f;
#pragma unroll
    for (int e = 0; e < NEXP; e++) { p[e] = expf(acc[e] - mx); Z += p[e]; }
    float inv = 1.f / Z;
#pragma unroll
    for (int e = 0; e < NEXP; e++) p[e] *= inv;
    int i0 = 0; float b0 = p[0];
#pragma unroll
    for (int e = 1; e < NEXP; e++) if (p[e] > b0) { b0 = p[e]; i0 = e; }
    int i1 = -1; float b1 = -1.f;
#pragma unroll
    for (int e = 0; e < NEXP; e++) if (e != i0 && p[e] > b1) { b1 = p[e]; i1 = e; }
    float s = b0 + b1 + 1e-9f;
    int pos0 = atomicAdd(&g_counts[i0], 1);
    g_list[i0 * NTOK + pos0] = n * 2;
    g_wts[n * 2] = b0 / s;
    int pos1 = atomicAdd(&g_counts[i1], 1);
    g_list[i1 * NTOK + pos1] = n * 2 + 1;
    g_wts[n * 2 + 1] = b1 / s;
  }
}

// ======== shared GEMM compute (R10-proven warp tile 64x32) ========
#define COMPUTE_TILE(sbuf)                                                        \
  {                                                                               \
    uint32_t as_ = smem_base + (sbuf)*STAGE_BYTES;                                \
    uint32_t bs_ = as_ + A_BYTES;                                                 \
    uint32_t arow_ = (lane & 15), asel_ = (lane >> 4) * 16;                       \
    _Pragma("unroll")                                                             \
    for (int kk = 0; kk < BK; kk += 16) {                                         \
      uint32_t af_[4][4], bf_[2][4];                                              \
      _Pragma("unroll")                                                           \
      for (int mi = 0; mi < 4; mi++)                                              \
        ldsm4(af_[mi], as_ + (wm + mi * 16 + arow_) * A_ROW_B + kk * 2 + asel_);  \
      _Pragma("unroll")                                                           \
      for (int nc = 0; nc < 2; nc++)                                              \
        ldsm4t(bf_[nc], bs_ + (kk + arow_) * B_ROW_B + (wn + nc * 16) * 2 + asel_);\
      _Pragma("unroll")                                                           \
      for (int mi = 0; mi < 4; mi++)                                              \
        _Pragma("unroll")                                                         \
        for (int nc = 0; nc < 2; nc++) {                                          \
          mma16816(acc[mi][2 * nc],     af_[mi], bf_[nc][0], bf_[nc][1]);         \
          mma16816(acc[mi][2 * nc + 1], af_[mi], bf_[nc][2], bf_[nc][3]);         \
        }                                                                         \
    }                                                                             \
  }

// generic load tile (used by gemm2)
#define LOAD_TILE(AROWS, ASTRIDE, BPTR, BSTRIDE, kt, sbuf)                        \
  {                                                                               \
    uint32_t as_ = smem_base + (sbuf)*STAGE_BYTES;                                \
    uint32_t bs_ = as_ + A_BYTES;                                                 \
    _Pragma("unroll")                                                             \
    for (int i_ = 0; i_ < 4; i_++) {                                              \
      int j_ = tid + 256 * i_;                                                    \
      int r_ = j_ >> 3, cc_ = j_ & 7;                                             \
      cp16(as_ + r_ * A_ROW_B + cc_ * 16, (AROWS) + (size_t)(ASTRIDE)[r_] * (size_t)(kt##_stride) + (kt) + cc_ * 8); \
    }                                                                             \
    _Pragma("unroll")                                                             \
    for (int i_ = 0; i_ < 4; i_++) {                                              \
      int j_ = tid + 256 * i_;                                                    \
      int r_ = j_ >> 4, cc_ = j_ & 15;                                            \
      cp16(bs_ + r_ * B_ROW_B + cc_ * 16, (BPTR) + (size_t)((kt) + r_) * (BSTRIDE) + cc_ * 8); \
    }                                                                             \
  }

#define GEMM_MAINLOOP(AROWS, ASTRIDE, BPTR, BSTRIDE, TT)   \
  _Pragma("unroll")                                        \
  for (int s = 0; s < STAGES - 1; s++) {                   \
    int kt = s * BK;                                       \
    LOAD_TILE(AROWS, ASTRIDE, BPTR, BSTRIDE, kt, s);       \
    CP_COMMIT();                                           \
  }                                                        \
  for (int t = 0; t < (TT); t++) {                         \
    CP_WAIT1();                                            \
    __syncthreads();                                       \
    int tn = t + STAGES - 1;                               \
    if (tn < (TT)) {                                       \
      int kt = tn * BK;                                    \
      LOAD_TILE(AROWS, ASTRIDE, BPTR, BSTRIDE, kt, tn % STAGES); \
    }                                                      \
    CP_COMMIT();                                           \
    COMPUTE_TILE(t % STAGES);                              \
  }

// gemm1 tile loader: segment = tn>>4 selects the A-row block, kt = (tn&15)*BK
#define LOAD_TILE1(tn, sbuf)                                                      \
  {                                                                               \
    uint32_t as_ = smem_base + (sbuf)*STAGE_BYTES;                                \
    uint32_t bs_ = as_ + A_BYTES;                                                 \
    const int seg_ = (tn) >> 4;                                                   \
    const int kt_ = ((tn) & 15) * BK;                                             \
    _Pragma("unroll")                                                             \
    for (int i_ = 0; i_ < 4; i_++) {                                              \
      int j_ = tid + 256 * i_;                                                    \
      int r_ = j_ >> 3, cc_ = j_ & 7;                                             \
      cp16(as_ + r_ * A_ROW_B + cc_ * 16,                                         \
           xh + (size_t)s_tok[seg_ * BM + r_] * CDIM + kt_ + cc_ * 8);            \
    }                                                                             \
    _Pragma("unroll")                                                             \
    for (int i_ = 0; i_ < 4; i_++) {                                              \
      int j_ = tid + 256 * i_;                                                    \
      int r_ = j_ >> 4, cc_ = j_ & 15;                                            \
      cp16(bs_ + r_ * B_ROW_B + cc_ * 16,                                         \
           BW + (size_t)(kt_ + r_) * HDIM + cc_ * 8);                             \
    }                                                                             \
  }

// ---------------- GEMM1  h = relu(gather(xh) @ W1h) — MSEGS m-tiles per block --
__global__ __launch_bounds__(256, 2) void gemm1_kernel(const __half* __restrict__ xh,
                                                       const __half* __restrict__ W1h) {
  const int e = blockIdx.z;
  const int cnt = g_counts[e];
  const int m0 = blockIdx.y * (MSEGS * BM);
  if (m0 >= cnt) return;
  const int nseg = (m0 + BM < cnt) ? 2 : 1;   // MSEGS==2
  const int TT = nseg * T1;
  const int n0 = blockIdx.x * BN;
  int base = 0;
#pragma unroll
  for (int i = 0; i < NEXP; i++) base += (i < e) ? g_counts[i] : 0;

  extern __shared__ char smem[];
  __shared__ int s_tok[MSEGS * BM];
  const uint32_t smem_base = smem_u32(smem);
  const int tid = threadIdx.x, wid = tid >> 5, lane = tid & 31;
  const int wm = (wid >> 2) * 64, wn = (wid & 3) * 32;

  {
    int m = m0 + tid;
    int idx = (m < cnt) ? m : (cnt - 1);
    s_tok[tid] = g_list[e * NTOK + idx] >> 1;
  }
  __syncthreads();

  const __half* BW = W1h + (size_t)e * CDIM * HDIM + n0;

  float acc[4][4][4];
#pragma unroll
  for (int a = 0; a < 4; a++)
#pragma unroll
    for (int b = 0; b < 4; b++)
#pragma unroll
      for (int c = 0; c < 4; c++) acc[a][b][c] = 0.f;

  const int rquad = lane >> 2, cpair = (lane & 3) * 2;

#pragma unroll
  for (int s = 0; s < STAGES - 1; s++) {
    LOAD_TILE1(s, s);
    CP_COMMIT();
  }
  for (int t = 0; t < TT; t++) {
    CP_WAIT1();
    __syncthreads();
    int tn = t + STAGES - 1;
    if (tn < TT) { LOAD_TILE1(tn, tn % STAGES); }
    CP_COMMIT();
    COMPUTE_TILE(t % STAGES);

    if ((t & (T1 - 1)) == (T1 - 1)) {
      // epilogue for segment t>>4: relu -> fp16 h rows, then reset acc
      const int mseg = m0 + (t >> 4) * BM;
#pragma unroll
      for (int mi = 0; mi < 4; mi++) {
        int rl0 = wm + mi * 16 + rquad;
#pragma unroll
        for (int ni = 0; ni < 4; ni++) {
          int col = n0 + wn + ni * 8 + cpair;
          if (mseg + rl0 < cnt) {
            __half2 h = __floats2half2_rn(fmaxf(acc[mi][ni][0], 0.f), fmaxf(acc[mi][ni][1], 0.f));
            *(__half2*)(g_hh + (size_t)(base + mseg + rl0) * HDIM + col) = h;
          }
          if (mseg + rl0 + 8 < cnt) {
            __half2 h = __floats2half2_rn(fmaxf(acc[mi][ni][2], 0.f), fmaxf(acc[mi][ni][3], 0.f));
            *(__half2*)(g_hh + (size_t)(base + mseg + rl0 + 8) * HDIM + col) = h;
          }
        }
      }
#pragma unroll
      for (int a = 0; a < 4; a++)
#pragma unroll
        for (int b = 0; b < 4; b++)
#pragma unroll
          for (int c = 0; c < 4; c++) acc[a][b][c] = 0.f;
    }
  }
}

// ---------------- GEMM2  y = w * (h @ W2h), stored fp16 ----------------
__global__ __launch_bounds__(256, 2) void gemm2_kernel(const __half* __restrict__ W2h) {
  const int e = blockIdx.z;
  const int cnt = g_counts[e];
  const int m0 = blockIdx.y * BM;
  if (m0 >= cnt) return;
  const int n0 = blockIdx.x * BN;
  int base = 0;
#pragma unroll
  for (int i = 0; i < NEXP; i++) base += (i < e) ? g_counts[i] : 0;

  extern __shared__ char smem[];
  __shared__ int s_row[BM];
  const uint32_t smem_base = smem_u32(smem);
  const int tid = threadIdx.x, wid = tid >> 5, lane = tid & 31;
  const int wm = (wid >> 2) * 64, wn = (wid & 3) * 32;

  if (tid < BM) {
    int m = m0 + tid;
    int idx = (m < cnt) ? m : (cnt - 1);
    s_row[tid] = base + idx;
  }
  __syncthreads();

  const __half* BW = W2h + (size_t)e * HDIM * CDIM + n0;
  const __half* Ah = g_hh;
  const int kt_stride = HDIM;

  float acc[4][4][4];
#pragma unroll
  for (int a = 0; a < 4; a++)
#pragma unroll
    for (int b = 0; b < 4; b++)
#pragma unroll
      for (int c = 0; c < 4; c++) acc[a][b][c] = 0.f;

  GEMM_MAINLOOP(Ah, s_row, BW, CDIM, T2);

  // epilogue: gate-weight scale, scatter fp16 pairs to per-assignment y row
  const int rquad = lane >> 2, cpair = (lane & 3) * 2;
#pragma unroll
  for (int mi = 0; mi < 4; mi++) {
    int rl0 = wm + mi * 16 + rquad;
#pragma unroll
    for (int half = 0; half < 2; half++) {
      int rl = rl0 + half * 8;
      if (m0 + rl < cnt) {
        int v = g_list[e * NTOK + m0 + rl];
        float w = g_wts[v];
        __half* yrow = g_yh + (size_t)v * CDIM + n0 + wn;
#pragma unroll
        for (int ni = 0; ni < 4; ni++) {
          __half2 o = __floats2half2_rn(w * acc[mi][ni][2 * half],
                                        w * acc[mi][ni][2 * half + 1]);
          *(__half2*)(yrow + ni * 8 + cpair) = o;
        }
      }
    }
  }
}

// ---------------- combine: out[n] = fp32(y[2n]) + fp32(y[2n+1]) ---------------
// Also re-zeros the expert counters for the next call (they are only read
// earlier in the pipeline; static zero-init covers the first call).
__global__ void combine_kernel(float* __restrict__ out) {
  if (blockIdx.x == 0 && threadIdx.x < NEXP) g_counts[threadIdx.x] = 0;
  int i = blockIdx.x * blockDim.x + threadIdx.x;  // 8-float chunk index
  int c8 = i & (CDIM / 8 - 1);
  int n = i >> 7;
  uint4 a = __ldcs((const uint4*)(g_yh + (size_t)(2 * n) * CDIM) + c8);
  uint4 b = __ldcs((const uint4*)(g_yh + (size_t)(2 * n + 1) * CDIM) + c8);
  const __half2* ah = (const __half2*)&a;
  const __half2* bh = (const __half2*)&b;
  float4 o0, o1;
  {
    float2 p = __half22float2(ah[0]), q = __half22float2(bh[0]);
    o0.x = p.x + q.x; o0.y = p.y + q.y;
    p = __half22float2(ah[1]); q = __half22float2(bh[1]);
    o0.z = p.x + q.x; o0.w = p.y + q.y;
    p = __half22float2(ah[2]); q = __half22float2(bh[2]);
    o1.x = p.x + q.x; o1.y = p.y + q.y;
    p = __half22float2(ah[3]); q = __half22float2(bh[3]);
    o1.z = p.x + q.x; o1.w = p.y + q.y;
  }
  ((float4*)out)[i * 2] = o0;
  ((float4*)out)[i * 2 + 1] = o1;
}

// ---------------- launch ----------------
extern "C" void kernel_launch(void* const* d_in, const int* in_sizes, int n_in,
                              void* d_out, int out_size) {
  const float* x  = (const float*)d_in[0];
  const float* Wg = (const float*)d_in[1];
  const float* W1 = (const float*)d_in[2];
  const float* W2 = (const float*)d_in[3];
  float* out = (float*)d_out;

  cudaFuncSetAttribute(gemm1_kernel, cudaFuncAttributeMaxDynamicSharedMemorySize, SMEM_DYN);
  cudaFuncSetAttribute(gemm2_kernel, cudaFuncAttributeMaxDynamicSharedMemorySize, SMEM_DYN);

  __half* xh = nullptr; __half* w1h = nullptr; __half* w2h = nullptr;
  cudaGetSymbolAddress((void**)&xh, g_xh);
  cudaGetSymbolAddress((void**)&w1h, g_w1h);
  cudaGetSymbolAddress((void**)&w2h, g_w2h);

  // 4 launches: prep(cvt||gating) -> gemm1 -> gemm2 -> combine(+count reset)
  prep_kernel<<<2 * WBLOCKS + GBLOCKS, 256>>>(W1, W2, w1h, w2h, x, Wg, xh);
  gemm1_kernel<<<dim3(HDIM / BN, NTOK / (MSEGS * BM), NEXP), 256, SMEM_DYN>>>(xh, w1h);
  gemm2_kernel<<<dim3(CDIM / BN, NTOK / BM, NEXP), 256, SMEM_DYN>>>(w2h);
  combine_kernel<<<NTOK * CDIM / 8 / 256, 256>>>(out);
}